// round 3
// baseline (speedup 1.0000x reference)
#include <cuda_runtime.h>
#include <cuda_bf16.h>
#include <math.h>

// ---------------- problem constants (fixed shapes) ----------------
#define B_  2
#define S_  2048
#define D_  1024
#define H_  16
#define KS  16      // splats per head
#define HD  64      // head dim
#define TD  (3*D_)  // qkv row width = 3072
#define IR  8       // influence radius

// ---------------- scratch (device globals; no allocation allowed) ----------------
__device__ float g_qkv[(size_t)B_ * S_ * TD];        // [B,S,3D]   50.3 MB
__device__ float g_ao [(size_t)B_ * S_ * D_];        // attn out [B,S,D] 16.8 MB
__device__ float g_qw [(size_t)B_ * H_ * S_ * KS];   // [B,H,S,K]  4.2 MB
__device__ float g_kw [(size_t)B_ * H_ * S_ * KS];
__device__ float g_mw [B_ * (S_-1)];                 // tanh(mag)
__device__ float g_im [B_ * (S_-1)];                 // 1/max(mag,1e-8)

// ======================================================================
// Trajectory kernels
// ======================================================================
__global__ void traj_mag_kernel(const float* __restrict__ x)
{
    int gw   = (blockIdx.x * blockDim.x + threadIdx.x) >> 5;
    int lane = threadIdx.x & 31;
    if (gw >= B_ * (S_ - 1)) return;
    int b = gw / (S_ - 1);
    int j = gw % (S_ - 1);
    const float* r0 = x + ((size_t)b * S_ + j) * D_;
    const float* r1 = r0 + D_;
    float ss = 0.f;
    #pragma unroll
    for (int it = 0; it < D_ / (32 * 4); ++it) {
        int d = lane * 4 + it * 128;
        float4 a = *(const float4*)(r0 + d);
        float4 c = *(const float4*)(r1 + d);
        float dx = c.x - a.x, dy = c.y - a.y, dz = c.z - a.z, dw = c.w - a.w;
        ss += dx*dx + dy*dy + dz*dz + dw*dw;
    }
    #pragma unroll
    for (int o = 16; o; o >>= 1) ss += __shfl_xor_sync(0xffffffffu, ss, o);
    if (lane == 0) {
        float mag = sqrtf(ss);
        g_im[b * (S_-1) + j] = 1.0f / fmaxf(mag, 1e-8f);
        g_mw[b * (S_-1) + j] = tanhf(mag);
    }
}

__global__ void traj_out_kernel(const float* __restrict__ x, float* __restrict__ traj)
{
    int p = blockIdx.x;
    int b = blockIdx.y;
    __shared__ float coef[IR];
    __shared__ int   sh_ws, sh_cnt;
    if (threadIdx.x == 0) {
        int ws  = p - IR; if (ws < 0) ws = 0;
        int cnt = p - ws;                       // <= 8
        float wsz = (float)(cnt > 0 ? cnt : 1);
        float w[IR]; float sum = 0.f;
        for (int t = 0; t < cnt; ++t) {
            float wv = g_mw[b * (S_-1) + ws + t] * (float)(t + 1) / wsz;
            w[t] = wv; sum += wv;
        }
        float inv = 1.0f / fmaxf(sum, 1e-8f);
        for (int t = 0; t < cnt; ++t)
            coef[t] = w[t] * inv * g_im[b * (S_-1) + ws + t];
        sh_ws = ws; sh_cnt = cnt;
    }
    __syncthreads();
    int ws = sh_ws, cnt = sh_cnt;
    const float* xb = x + (size_t)b * S_ * D_;
    for (int d = threadIdx.x * 4; d < D_; d += blockDim.x * 4) {
        float4 a = make_float4(0.f, 0.f, 0.f, 0.f);
        for (int t = 0; t < cnt; ++t) {
            float c = coef[t];
            const float* r0 = xb + (size_t)(ws + t) * D_ + d;
            float4 u = *(const float4*)(r0);
            float4 v = *(const float4*)(r0 + D_);
            a.x += c * (v.x - u.x); a.y += c * (v.y - u.y);
            a.z += c * (v.z - u.z); a.w += c * (v.w - u.w);
        }
        *(float4*)(traj + ((size_t)b * S_ + p) * D_ + d) = a;
    }
}

// ======================================================================
// SGEMM: C[M,N] = A[M,K] * B[N,K]^T   (both row-major, K contiguous)
// 128x128x16 tiles, 8x8 microtile, 256 threads, smem double buffering
// ======================================================================
__device__ __forceinline__ void sgemm_body(const float* __restrict__ A,
                                           const float* __restrict__ Bm,
                                           float* __restrict__ C,
                                           int M, int N, int K)
{
    __shared__ float As[2][16][128];
    __shared__ float Bs[2][16][128];
    const int tid = threadIdx.x;
    const int m0 = blockIdx.y * 128;
    const int n0 = blockIdx.x * 128;
    const int tx = tid & 15;   // n micro
    const int ty = tid >> 4;   // m micro

    const int lrow = tid >> 2;          // 0..63
    const int lk   = (tid & 3) * 4;     // 0,4,8,12

    const float* Ap = A  + (size_t)(m0 + lrow) * K + lk;
    const float* Bp = Bm + (size_t)(n0 + lrow) * K + lk;

    float acc[8][8];
    #pragma unroll
    for (int i = 0; i < 8; ++i)
        #pragma unroll
        for (int j = 0; j < 8; ++j) acc[i][j] = 0.f;

    // preload tile 0
    {
        float4 a0 = *(const float4*)(Ap);
        float4 a1 = *(const float4*)(Ap + (size_t)64 * K);
        float4 b0 = *(const float4*)(Bp);
        float4 b1 = *(const float4*)(Bp + (size_t)64 * K);
        As[0][lk+0][lrow]    = a0.x; As[0][lk+1][lrow]    = a0.y;
        As[0][lk+2][lrow]    = a0.z; As[0][lk+3][lrow]    = a0.w;
        As[0][lk+0][lrow+64] = a1.x; As[0][lk+1][lrow+64] = a1.y;
        As[0][lk+2][lrow+64] = a1.z; As[0][lk+3][lrow+64] = a1.w;
        Bs[0][lk+0][lrow]    = b0.x; Bs[0][lk+1][lrow]    = b0.y;
        Bs[0][lk+2][lrow]    = b0.z; Bs[0][lk+3][lrow]    = b0.w;
        Bs[0][lk+0][lrow+64] = b1.x; Bs[0][lk+1][lrow+64] = b1.y;
        Bs[0][lk+2][lrow+64] = b1.z; Bs[0][lk+3][lrow+64] = b1.w;
    }
    __syncthreads();

    int buf = 0;
    const int T = K >> 4;
    for (int t = 0; t < T; ++t) {
        float4 pa0, pa1, pb0, pb1;
        const bool more = (t + 1 < T);
        if (more) {
            const float* Ap2 = Ap + ((t + 1) << 4);
            const float* Bp2 = Bp + ((t + 1) << 4);
            pa0 = *(const float4*)(Ap2);
            pa1 = *(const float4*)(Ap2 + (size_t)64 * K);
            pb0 = *(const float4*)(Bp2);
            pb1 = *(const float4*)(Bp2 + (size_t)64 * K);
        }
        #pragma unroll
        for (int kk = 0; kk < 16; ++kk) {
            float4 ra0 = *(const float4*)&As[buf][kk][ty * 8];
            float4 ra1 = *(const float4*)&As[buf][kk][ty * 8 + 4];
            float4 rb0 = *(const float4*)&Bs[buf][kk][tx * 8];
            float4 rb1 = *(const float4*)&Bs[buf][kk][tx * 8 + 4];
            float ra[8] = {ra0.x, ra0.y, ra0.z, ra0.w, ra1.x, ra1.y, ra1.z, ra1.w};
            float rb[8] = {rb0.x, rb0.y, rb0.z, rb0.w, rb1.x, rb1.y, rb1.z, rb1.w};
            #pragma unroll
            for (int i = 0; i < 8; ++i)
                #pragma unroll
                for (int j = 0; j < 8; ++j)
                    acc[i][j] = fmaf(ra[i], rb[j], acc[i][j]);
        }
        if (more) {
            int nb = buf ^ 1;
            As[nb][lk+0][lrow]    = pa0.x; As[nb][lk+1][lrow]    = pa0.y;
            As[nb][lk+2][lrow]    = pa0.z; As[nb][lk+3][lrow]    = pa0.w;
            As[nb][lk+0][lrow+64] = pa1.x; As[nb][lk+1][lrow+64] = pa1.y;
            As[nb][lk+2][lrow+64] = pa1.z; As[nb][lk+3][lrow+64] = pa1.w;
            Bs[nb][lk+0][lrow]    = pb0.x; Bs[nb][lk+1][lrow]    = pb0.y;
            Bs[nb][lk+2][lrow]    = pb0.z; Bs[nb][lk+3][lrow]    = pb0.w;
            Bs[nb][lk+0][lrow+64] = pb1.x; Bs[nb][lk+1][lrow+64] = pb1.y;
            Bs[nb][lk+2][lrow+64] = pb1.z; Bs[nb][lk+3][lrow+64] = pb1.w;
        }
        __syncthreads();
        buf ^= 1;
    }

    #pragma unroll
    for (int i = 0; i < 8; ++i) {
        float* Cp = C + (size_t)(m0 + ty * 8 + i) * N + n0 + tx * 8;
        float4 o0 = make_float4(acc[i][0], acc[i][1], acc[i][2], acc[i][3]);
        float4 o1 = make_float4(acc[i][4], acc[i][5], acc[i][6], acc[i][7]);
        *(float4*)(Cp)     = o0;
        *(float4*)(Cp + 4) = o1;
    }
}

__global__ __launch_bounds__(256, 2)
void sgemm_qkv_kernel(const float* __restrict__ x, const float* __restrict__ w)
{
    sgemm_body(x, w, g_qkv, B_ * S_, TD, D_);
}

__global__ __launch_bounds__(256, 2)
void sgemm_out_kernel(const float* __restrict__ w, float* __restrict__ out)
{
    sgemm_body(g_ao, w, out, B_ * S_, D_, D_);
}

// ======================================================================
// Splat weights: w[b,h,s,k] = sigmoid(amp) * exp(-0.5*dist_sq/exp(ls)^2)
// ======================================================================
__global__ __launch_bounds__(256)
void splat_weights_kernel(const float* __restrict__ centers,
                          const float* __restrict__ lsc,
                          const float* __restrict__ amp,
                          int off, int which)  // which: 0 -> g_qw, 1 -> g_kw
{
    int b  = blockIdx.z, h = blockIdx.y;
    int s0 = blockIdx.x * 128;
    int tid = threadIdx.x;
    float* out = which ? g_kw : g_qw;

    __shared__ float cs[KS][HD];
    __shared__ float cn[KS], fac[KS], am[KS];
    __shared__ float ts[128][HD];

    #pragma unroll
    for (int it = 0; it < 4; ++it) {
        int idx = tid + it * 256;        // 1024 = 16*64
        int kk = idx >> 6, d = idx & 63;
        cs[kk][d] = centers[((size_t)h * KS + kk) * HD + d];
    }
    if (tid < KS) {
        float ls = lsc[h * KS + tid];
        fac[tid] = -0.5f * __expf(-2.0f * ls);   // -0.5 / exp(ls)^2
        float a  = amp[h * KS + tid];
        am[tid]  = 1.0f / (1.0f + __expf(-a));
    }
    __syncthreads();
    if (tid < KS) {
        float s = 0.f;
        #pragma unroll
        for (int d = 0; d < HD; ++d) { float c = cs[tid][d]; s += c * c; }
        cn[tid] = s;
    }
    // load the 128 x 64 token slice
    const float* base = g_qkv + ((size_t)b * S_ + s0) * TD + off + h * HD;
    #pragma unroll
    for (int it = 0; it < 8; ++it) {
        int idx = tid + it * 256;        // 2048 float4
        int s = idx >> 4, c4 = (idx & 15) * 4;
        *(float4*)&ts[s][c4] = *(const float4*)(base + (size_t)s * TD + c4);
    }
    __syncthreads();

    #pragma unroll
    for (int it = 0; it < 8; ++it) {
        int idx = tid + it * 256;
        int s = idx >> 4, kk = idx & 15;
        float cross = 0.f, tn = 0.f;
        #pragma unroll
        for (int d = 0; d < HD; ++d) {
            float tv = ts[s][d];
            cross = fmaf(tv, cs[kk][d], cross);
            tn    = fmaf(tv, tv, tn);
        }
        float dist = tn - 2.0f * cross + cn[kk];
        out[(((size_t)b * H_ + h) * S_ + s0 + s) * KS + kk] =
            __expf(fac[kk] * dist) * am[kk];
    }
}

// ======================================================================
// Fused attention: per (b,h) flash-style, 1 thread = 1 query row.
// logits = sum_k qw*kw >= 0 and <= 16 -> exp() needs no max subtraction.
// ======================================================================
__global__ __launch_bounds__(128)
void attn_kernel()
{
    int b  = blockIdx.z, h = blockIdx.y;
    int i0 = blockIdx.x * 128;
    int tid = threadIdx.x;

    __shared__ float kws[64][KS];
    __shared__ float vs[64][HD];

    const float* qwp = g_qw + (((size_t)b * H_ + h) * S_ + i0 + tid) * KS;
    float qw[KS];
    #pragma unroll
    for (int k = 0; k < KS; ++k) qw[k] = qwp[k];

    float acc[HD];
    #pragma unroll
    for (int d = 0; d < HD; ++d) acc[d] = 0.f;
    float den = 0.f;

    const float* kwb = g_kw + ((size_t)b * H_ + h) * S_ * KS;
    const float* vb  = g_qkv + (size_t)b * S_ * TD + 2 * D_ + h * HD;

    for (int j0 = 0; j0 < S_; j0 += 64) {
        #pragma unroll
        for (int it = 0; it < 2; ++it) {               // 64*16 floats = 256 f4
            int idx = tid + it * 128;
            int j = idx >> 2, c4 = (idx & 3) * 4;
            *(float4*)&kws[j][c4] = *(const float4*)(kwb + (size_t)(j0 + j) * KS + c4);
        }
        #pragma unroll
        for (int it = 0; it < 8; ++it) {               // 64*64 floats = 1024 f4
            int idx = tid + it * 128;
            int j = idx >> 4, c4 = (idx & 15) * 4;
            *(float4*)&vs[j][c4] = *(const float4*)(vb + (size_t)(j0 + j) * TD + c4);
        }
        __syncthreads();

        #pragma unroll 2
        for (int jj = 0; jj < 64; ++jj) {
            float4 k0 = *(const float4*)&kws[jj][0];
            float4 k1 = *(const float4*)&kws[jj][4];
            float4 k2 = *(const float4*)&kws[jj][8];
            float4 k3 = *(const float4*)&kws[jj][12];
            float z = qw[0]*k0.x + qw[1]*k0.y + qw[2]*k0.z + qw[3]*k0.w
                    + qw[4]*k1.x + qw[5]*k1.y + qw[6]*k1.z + qw[7]*k1.w
                    + qw[8]*k2.x + qw[9]*k2.y + qw[10]*k2.z + qw[11]*k2.w
                    + qw[12]*k3.x + qw[13]*k3.y + qw[14]*k3.z + qw[15]*k3.w;
            float e = __expf(z);
            den += e;
            const float4* vp = (const float4*)vs[jj];
            #pragma unroll
            for (int d4 = 0; d4 < 16; ++d4) {
                float4 vv = vp[d4];
                acc[4*d4+0] = fmaf(e, vv.x, acc[4*d4+0]);
                acc[4*d4+1] = fmaf(e, vv.y, acc[4*d4+1]);
                acc[4*d4+2] = fmaf(e, vv.z, acc[4*d4+2]);
                acc[4*d4+3] = fmaf(e, vv.w, acc[4*d4+3]);
            }
        }
        __syncthreads();
    }

    float inv = 1.0f / den;
    float* op = g_ao + ((size_t)b * S_ + i0 + tid) * D_ + h * HD;
    #pragma unroll
    for (int d4 = 0; d4 < 16; ++d4) {
        float4 o = make_float4(acc[4*d4+0]*inv, acc[4*d4+1]*inv,
                               acc[4*d4+2]*inv, acc[4*d4+3]*inv);
        *(float4*)(op + 4*d4) = o;
    }
}

// ======================================================================
// launch
// ======================================================================
extern "C" void kernel_launch(void* const* d_in, const int* in_sizes, int n_in,
                              void* d_out, int out_size)
{
    const float* x       = (const float*)d_in[0];
    const float* qkv_w   = (const float*)d_in[1];
    const float* out_w   = (const float*)d_in[2];
    const float* centers = (const float*)d_in[3];
    const float* lsc     = (const float*)d_in[4];
    const float* amps    = (const float*)d_in[5];
    float* out = (float*)d_out;

    const int BSD = B_ * S_ * D_;

    // trajectories (independent branch) -> second half of d_out
    {
        int warps = B_ * (S_ - 1);
        int blocks = (warps * 32 + 127) / 128;
        traj_mag_kernel<<<blocks, 128>>>(x);
        if (out_size >= 2 * BSD) {
            traj_out_kernel<<<dim3(S_, B_), 256>>>(x, out + BSD);
        }
    }

    // qkv projection
    sgemm_qkv_kernel<<<dim3(TD / 128, (B_ * S_) / 128), 256>>>(x, qkv_w);

    // splat weights for q and k
    splat_weights_kernel<<<dim3(S_ / 128, H_, B_), 256>>>(centers, lsc, amps, 0,  0);
    splat_weights_kernel<<<dim3(S_ / 128, H_, B_), 256>>>(centers, lsc, amps, D_, 1);

    // fused attention
    attn_kernel<<<dim3(S_ / 128, H_, B_), 128>>>();

    // output projection -> first half of d_out
    sgemm_out_kernel<<<dim3(D_ / 128, (B_ * S_) / 128), 256>>>(out_w, out);
}

// round 4
// speedup vs baseline: 1.8413x; 1.8413x over previous
#include <cuda_runtime.h>
#include <cuda_bf16.h>
#include <math.h>

// ---------------- problem constants (fixed shapes) ----------------
#define B_  2
#define S_  2048
#define D_  1024
#define H_  16
#define KS  16      // splats per head
#define HD  64      // head dim
#define TD  (3*D_)  // qkv row width = 3072
#define IR  8       // influence radius

typedef unsigned long long u64;

// ---------------- packed f32x2 helpers ----------------
__device__ __forceinline__ u64 pk2(float lo, float hi) {
    u64 r; asm("mov.b64 %0, {%1, %2};" : "=l"(r) : "f"(lo), "f"(hi)); return r;
}
__device__ __forceinline__ u64 pk1(float v) { return pk2(v, v); }
__device__ __forceinline__ float2 up2(u64 v) {
    float2 r; asm("mov.b64 {%0, %1}, %2;" : "=f"(r.x), "=f"(r.y) : "l"(v)); return r;
}
__device__ __forceinline__ u64 ffma2(u64 a, u64 b, u64 c) {
    u64 d; asm("fma.rn.f32x2 %0, %1, %2, %3;" : "=l"(d) : "l"(a), "l"(b), "l"(c));
    return d;
}

// ---------------- scratch (device globals; no allocation allowed) ----------------
__device__ float g_qkv[(size_t)B_ * S_ * TD];        // [B,S,3D]
__device__ float g_ao [(size_t)B_ * S_ * D_];        // attn out [B,S,D]
__device__ float g_qw [(size_t)B_ * H_ * S_ * KS];   // [B,H,S,K]
__device__ float g_kw [(size_t)B_ * H_ * S_ * KS];
__device__ float g_mw [B_ * (S_-1)];                 // tanh(mag)
__device__ float g_im [B_ * (S_-1)];                 // 1/max(mag,1e-8)

// ======================================================================
// Trajectory kernels
// ======================================================================
__global__ void traj_mag_kernel(const float* __restrict__ x)
{
    int gw   = (blockIdx.x * blockDim.x + threadIdx.x) >> 5;
    int lane = threadIdx.x & 31;
    if (gw >= B_ * (S_ - 1)) return;
    int b = gw / (S_ - 1);
    int j = gw % (S_ - 1);
    const float* r0 = x + ((size_t)b * S_ + j) * D_;
    const float* r1 = r0 + D_;
    float ss = 0.f;
    #pragma unroll
    for (int it = 0; it < D_ / (32 * 4); ++it) {
        int d = lane * 4 + it * 128;
        float4 a = *(const float4*)(r0 + d);
        float4 c = *(const float4*)(r1 + d);
        float dx = c.x - a.x, dy = c.y - a.y, dz = c.z - a.z, dw = c.w - a.w;
        ss += dx*dx + dy*dy + dz*dz + dw*dw;
    }
    #pragma unroll
    for (int o = 16; o; o >>= 1) ss += __shfl_xor_sync(0xffffffffu, ss, o);
    if (lane == 0) {
        float mag = sqrtf(ss);
        g_im[b * (S_-1) + j] = 1.0f / fmaxf(mag, 1e-8f);
        g_mw[b * (S_-1) + j] = tanhf(mag);
    }
}

__global__ void traj_out_kernel(const float* __restrict__ x, float* __restrict__ traj)
{
    int p = blockIdx.x;
    int b = blockIdx.y;
    __shared__ float coef[IR];
    __shared__ int   sh_ws, sh_cnt;
    if (threadIdx.x == 0) {
        int ws  = p - IR; if (ws < 0) ws = 0;
        int cnt = p - ws;                       // <= 8
        float wsz = (float)(cnt > 0 ? cnt : 1);
        float w[IR]; float sum = 0.f;
        for (int t = 0; t < cnt; ++t) {
            float wv = g_mw[b * (S_-1) + ws + t] * (float)(t + 1) / wsz;
            w[t] = wv; sum += wv;
        }
        float inv = 1.0f / fmaxf(sum, 1e-8f);
        for (int t = 0; t < cnt; ++t)
            coef[t] = w[t] * inv * g_im[b * (S_-1) + ws + t];
        sh_ws = ws; sh_cnt = cnt;
    }
    __syncthreads();
    int ws = sh_ws, cnt = sh_cnt;
    const float* xb = x + (size_t)b * S_ * D_;
    for (int d = threadIdx.x * 4; d < D_; d += blockDim.x * 4) {
        float4 a = make_float4(0.f, 0.f, 0.f, 0.f);
        for (int t = 0; t < cnt; ++t) {
            float c = coef[t];
            const float* r0 = xb + (size_t)(ws + t) * D_ + d;
            float4 u = *(const float4*)(r0);
            float4 v = *(const float4*)(r0 + D_);
            a.x += c * (v.x - u.x); a.y += c * (v.y - u.y);
            a.z += c * (v.z - u.z); a.w += c * (v.w - u.w);
        }
        *(float4*)(traj + ((size_t)b * S_ + p) * D_ + d) = a;
    }
}

// ======================================================================
// SGEMM: C[M,N] = A[M,K] * B[N,K]^T   (both row-major, K contiguous)
// 128x128x16 tiles, 8x8 microtile (packed f32x2 along n), 256 threads
// ======================================================================
__device__ __forceinline__ void sgemm_body(const float* __restrict__ A,
                                           const float* __restrict__ Bm,
                                           float* __restrict__ C,
                                           int M, int N, int K)
{
    __shared__ __align__(16) float As[2][16][128];
    __shared__ __align__(16) float Bs[2][16][128];
    const int tid = threadIdx.x;
    const int m0 = blockIdx.y * 128;
    const int n0 = blockIdx.x * 128;
    const int tx = tid & 15;   // n micro
    const int ty = tid >> 4;   // m micro

    const int lrow = tid >> 2;          // 0..63
    const int lk   = (tid & 3) * 4;     // 0,4,8,12

    const float* Ap = A  + (size_t)(m0 + lrow) * K + lk;
    const float* Bp = Bm + (size_t)(n0 + lrow) * K + lk;

    u64 accp[8][4];
    #pragma unroll
    for (int i = 0; i < 8; ++i)
        #pragma unroll
        for (int j = 0; j < 4; ++j) accp[i][j] = 0ull;   // (0.0f, 0.0f)

    // preload tile 0
    {
        float4 a0 = *(const float4*)(Ap);
        float4 a1 = *(const float4*)(Ap + (size_t)64 * K);
        float4 b0 = *(const float4*)(Bp);
        float4 b1 = *(const float4*)(Bp + (size_t)64 * K);
        As[0][lk+0][lrow]    = a0.x; As[0][lk+1][lrow]    = a0.y;
        As[0][lk+2][lrow]    = a0.z; As[0][lk+3][lrow]    = a0.w;
        As[0][lk+0][lrow+64] = a1.x; As[0][lk+1][lrow+64] = a1.y;
        As[0][lk+2][lrow+64] = a1.z; As[0][lk+3][lrow+64] = a1.w;
        Bs[0][lk+0][lrow]    = b0.x; Bs[0][lk+1][lrow]    = b0.y;
        Bs[0][lk+2][lrow]    = b0.z; Bs[0][lk+3][lrow]    = b0.w;
        Bs[0][lk+0][lrow+64] = b1.x; Bs[0][lk+1][lrow+64] = b1.y;
        Bs[0][lk+2][lrow+64] = b1.z; Bs[0][lk+3][lrow+64] = b1.w;
    }
    __syncthreads();

    int buf = 0;
    const int T = K >> 4;
    for (int t = 0; t < T; ++t) {
        float4 pa0, pa1, pb0, pb1;
        const bool more = (t + 1 < T);
        if (more) {
            const float* Ap2 = Ap + ((t + 1) << 4);
            const float* Bp2 = Bp + ((t + 1) << 4);
            pa0 = *(const float4*)(Ap2);
            pa1 = *(const float4*)(Ap2 + (size_t)64 * K);
            pb0 = *(const float4*)(Bp2);
            pb1 = *(const float4*)(Bp2 + (size_t)64 * K);
        }
        #pragma unroll
        for (int kk = 0; kk < 16; ++kk) {
            float4 ra0 = *(const float4*)&As[buf][kk][ty * 8];
            float4 ra1 = *(const float4*)&As[buf][kk][ty * 8 + 4];
            const ulonglong2* bpr = (const ulonglong2*)&Bs[buf][kk][tx * 8];
            ulonglong2 rb01 = bpr[0];
            ulonglong2 rb23 = bpr[1];
            u64 rbp[4] = { rb01.x, rb01.y, rb23.x, rb23.y };
            u64 rap[8] = { pk1(ra0.x), pk1(ra0.y), pk1(ra0.z), pk1(ra0.w),
                           pk1(ra1.x), pk1(ra1.y), pk1(ra1.z), pk1(ra1.w) };
            #pragma unroll
            for (int i = 0; i < 8; ++i)
                #pragma unroll
                for (int j = 0; j < 4; ++j)
                    accp[i][j] = ffma2(rap[i], rbp[j], accp[i][j]);
        }
        if (more) {
            int nb = buf ^ 1;
            As[nb][lk+0][lrow]    = pa0.x; As[nb][lk+1][lrow]    = pa0.y;
            As[nb][lk+2][lrow]    = pa0.z; As[nb][lk+3][lrow]    = pa0.w;
            As[nb][lk+0][lrow+64] = pa1.x; As[nb][lk+1][lrow+64] = pa1.y;
            As[nb][lk+2][lrow+64] = pa1.z; As[nb][lk+3][lrow+64] = pa1.w;
            Bs[nb][lk+0][lrow]    = pb0.x; Bs[nb][lk+1][lrow]    = pb0.y;
            Bs[nb][lk+2][lrow]    = pb0.z; Bs[nb][lk+3][lrow]    = pb0.w;
            Bs[nb][lk+0][lrow+64] = pb1.x; Bs[nb][lk+1][lrow+64] = pb1.y;
            Bs[nb][lk+2][lrow+64] = pb1.z; Bs[nb][lk+3][lrow+64] = pb1.w;
        }
        __syncthreads();
        buf ^= 1;
    }

    #pragma unroll
    for (int i = 0; i < 8; ++i) {
        float* Cp = C + (size_t)(m0 + ty * 8 + i) * N + n0 + tx * 8;
        ulonglong2 o0 = make_ulonglong2(accp[i][0], accp[i][1]);
        ulonglong2 o1 = make_ulonglong2(accp[i][2], accp[i][3]);
        *(ulonglong2*)(Cp)     = o0;
        *(ulonglong2*)(Cp + 4) = o1;
    }
}

__global__ __launch_bounds__(256, 2)
void sgemm_qkv_kernel(const float* __restrict__ x, const float* __restrict__ w)
{
    sgemm_body(x, w, g_qkv, B_ * S_, TD, D_);
}

__global__ __launch_bounds__(256, 2)
void sgemm_out_kernel(const float* __restrict__ w, float* __restrict__ out)
{
    sgemm_body(g_ao, w, out, B_ * S_, D_, D_);
}

// ======================================================================
// Splat weights: w[b,h,s,k] = sigmoid(amp) * exp(-0.5*dist_sq/exp(ls)^2)
// fused q+k via blockIdx.z; token-norm precomputed once; packed dot.
// ======================================================================
__global__ __launch_bounds__(256)
void splat_weights_kernel(const float* __restrict__ centers,
                          const float* __restrict__ lsc,
                          const float* __restrict__ amp)
{
    int z = blockIdx.z;
    int which = z & 1;            // 0 -> q, 1 -> k
    int b = z >> 1;
    int h = blockIdx.y;
    int s0 = blockIdx.x * 128;
    int tid = threadIdx.x;
    int off = which ? D_ : 0;
    float* outp = which ? g_kw : g_qw;

    __shared__ __align__(16) float cs[KS][HD];
    __shared__ float cn[KS], fac[KS], am[KS];
    __shared__ __align__(16) float ts[128][HD];
    __shared__ float tn[128];

    #pragma unroll
    for (int it = 0; it < 4; ++it) {
        int idx = tid + it * 256;        // 1024 = 16*64
        int kk = idx >> 6, d = idx & 63;
        cs[kk][d] = centers[((size_t)h * KS + kk) * HD + d];
    }
    if (tid < KS) {
        float ls = lsc[h * KS + tid];
        fac[tid] = -0.5f * __expf(-2.0f * ls);   // -0.5 / exp(ls)^2
        float a  = amp[h * KS + tid];
        am[tid]  = 1.0f / (1.0f + __expf(-a));
    }
    // load the 128 x 64 token slice
    const float* base = g_qkv + ((size_t)b * S_ + s0) * TD + off + h * HD;
    #pragma unroll
    for (int it = 0; it < 8; ++it) {
        int idx = tid + it * 256;        // 2048 float4
        int s = idx >> 4, c4 = (idx & 15) * 4;
        *(float4*)&ts[s][c4] = *(const float4*)(base + (size_t)s * TD + c4);
    }
    __syncthreads();
    if (tid < KS) {
        float s = 0.f;
        #pragma unroll
        for (int d = 0; d < HD; ++d) { float c = cs[tid][d]; s += c * c; }
        cn[tid] = s;
    }
    if (tid < 128) {
        const u64* tp = (const u64*)&ts[tid][0];
        u64 acc = 0ull;
        #pragma unroll
        for (int d = 0; d < 32; ++d) acc = ffma2(tp[d], tp[d], acc);
        float2 u = up2(acc);
        tn[tid] = u.x + u.y;
    }
    __syncthreads();

    #pragma unroll
    for (int it = 0; it < 8; ++it) {
        int idx = tid + it * 256;
        int s = idx >> 4, kk = idx & 15;
        const u64* tp = (const u64*)&ts[s][0];
        const u64* cp = (const u64*)&cs[kk][0];
        u64 acc = 0ull;
        #pragma unroll
        for (int d = 0; d < 32; ++d) acc = ffma2(tp[d], cp[d], acc);
        float2 u = up2(acc);
        float cross = u.x + u.y;
        float dist = tn[s] - 2.0f * cross + cn[kk];
        outp[(((size_t)b * H_ + h) * S_ + s0 + s) * KS + kk] =
            __expf(fac[kk] * dist) * am[kk];
    }
}

// ======================================================================
// Fused attention: per (b,h) flash-style, 1 thread = 1 query row.
// logits in [0,16] -> exp() needs no max subtraction. Packed f32x2.
// ======================================================================
__global__ __launch_bounds__(128)
void attn_kernel()
{
    int b  = blockIdx.z, h = blockIdx.y;
    int i0 = blockIdx.x * 128;
    int tid = threadIdx.x;

    __shared__ __align__(16) float kws[64][KS];
    __shared__ __align__(16) float vs[64][HD];

    const float* qwf = g_qw + (((size_t)b * H_ + h) * S_ + i0 + tid) * KS;
    u64 qwp[8];
    {
        const ulonglong2* qp = (const ulonglong2*)qwf;
        #pragma unroll
        for (int t = 0; t < 4; ++t) {
            ulonglong2 v = qp[t];
            qwp[2*t]   = v.x;
            qwp[2*t+1] = v.y;
        }
    }

    u64 accp[32];
    #pragma unroll
    for (int d = 0; d < 32; ++d) accp[d] = 0ull;
    float den = 0.f;

    const float* kwb = g_kw + ((size_t)b * H_ + h) * S_ * KS;
    const float* vb  = g_qkv + (size_t)b * S_ * TD + 2 * D_ + h * HD;

    for (int j0 = 0; j0 < S_; j0 += 64) {
        #pragma unroll
        for (int it = 0; it < 2; ++it) {               // 64*16 floats = 256 f4
            int idx = tid + it * 128;
            int j = idx >> 2, c4 = (idx & 3) * 4;
            *(float4*)&kws[j][c4] = *(const float4*)(kwb + (size_t)(j0 + j) * KS + c4);
        }
        #pragma unroll
        for (int it = 0; it < 8; ++it) {               // 64*64 floats = 1024 f4
            int idx = tid + it * 128;
            int j = idx >> 4, c4 = (idx & 15) * 4;
            *(float4*)&vs[j][c4] = *(const float4*)(vb + (size_t)(j0 + j) * TD + c4);
        }
        __syncthreads();

        #pragma unroll 2
        for (int jj = 0; jj < 64; ++jj) {
            const u64* kp = (const u64*)&kws[jj][0];
            u64 zp = 0ull;
            #pragma unroll
            for (int t = 0; t < 8; ++t) zp = ffma2(qwp[t], kp[t], zp);
            float2 zu = up2(zp);
            float e = __expf(zu.x + zu.y);
            den += e;
            u64 ep = pk1(e);
            const u64* vp = (const u64*)&vs[jj][0];
            #pragma unroll
            for (int d = 0; d < 32; ++d)
                accp[d] = ffma2(ep, vp[d], accp[d]);
        }
        __syncthreads();
    }

    float inv = 1.0f / den;
    float* op = g_ao + ((size_t)b * S_ + i0 + tid) * D_ + h * HD;
    #pragma unroll
    for (int d2 = 0; d2 < 16; ++d2) {
        float2 a0 = up2(accp[2*d2]);
        float2 a1 = up2(accp[2*d2+1]);
        float4 o = make_float4(a0.x * inv, a0.y * inv, a1.x * inv, a1.y * inv);
        *(float4*)(op + 4*d2) = o;
    }
}

// ======================================================================
// launch
// ======================================================================
extern "C" void kernel_launch(void* const* d_in, const int* in_sizes, int n_in,
                              void* d_out, int out_size)
{
    const float* x       = (const float*)d_in[0];
    const float* qkv_w   = (const float*)d_in[1];
    const float* out_w   = (const float*)d_in[2];
    const float* centers = (const float*)d_in[3];
    const float* lsc     = (const float*)d_in[4];
    const float* amps    = (const float*)d_in[5];
    float* out = (float*)d_out;

    const int BSD = B_ * S_ * D_;

    // trajectories (independent branch) -> second half of d_out
    {
        int warps = B_ * (S_ - 1);
        int blocks = (warps * 32 + 127) / 128;
        traj_mag_kernel<<<blocks, 128>>>(x);
        if (out_size >= 2 * BSD) {
            traj_out_kernel<<<dim3(S_, B_), 256>>>(x, out + BSD);
        }
    }

    // qkv projection
    sgemm_qkv_kernel<<<dim3(TD / 128, (B_ * S_) / 128), 256>>>(x, qkv_w);

    // splat weights for q and k (fused: grid.z = 2*B)
    splat_weights_kernel<<<dim3(S_ / 128, H_, 2 * B_), 256>>>(centers, lsc, amps);

    // fused attention
    attn_kernel<<<dim3(S_ / 128, H_, B_), 128>>>();

    // output projection -> first half of d_out
    sgemm_out_kernel<<<dim3(D_ / 128, (B_ * S_) / 128), 256>>>(out_w, out);
}

// round 9
// speedup vs baseline: 2.5475x; 1.3836x over previous
#include <cuda_runtime.h>
#include <cuda_bf16.h>
#include <math.h>
#include <stdint.h>

// ---------------- problem constants (fixed shapes) ----------------
#define B_  2
#define S_  2048
#define D_  1024
#define H_  16
#define KS  16      // splats per head
#define HD  64      // head dim
#define TD  (3*D_)  // qkv row width = 3072
#define IR  8       // influence radius
#define KDIM 1024   // GEMM K for both projections

typedef unsigned long long u64;

// ---------------- packed f32x2 helpers ----------------
__device__ __forceinline__ u64 pk2(float lo, float hi) {
    u64 r; asm("mov.b64 %0, {%1, %2};" : "=l"(r) : "f"(lo), "f"(hi)); return r;
}
__device__ __forceinline__ u64 pk1(float v) { return pk2(v, v); }
__device__ __forceinline__ float2 up2(u64 v) {
    float2 r; asm("mov.b64 {%0, %1}, %2;" : "=f"(r.x), "=f"(r.y) : "l"(v)); return r;
}
__device__ __forceinline__ u64 ffma2(u64 a, u64 b, u64 c) {
    u64 d; asm("fma.rn.f32x2 %0, %1, %2, %3;" : "=l"(d) : "l"(a), "l"(b), "l"(c));
    return d;
}

// ---------------- warp MMA helpers (sm_80 baseline PTX; runs on sm_103) ----
__device__ __forceinline__ uint32_t smem_u32(const void* p) {
    uint32_t a;
    asm("{ .reg .u64 t; cvta.to.shared.u64 t, %1; cvt.u32.u64 %0, t; }" : "=r"(a) : "l"(p));
    return a;
}
__device__ __forceinline__ void ldsm4(uint32_t addr, uint32_t* r) {
    asm volatile("ldmatrix.sync.aligned.m8n8.x4.shared.b16 {%0,%1,%2,%3}, [%4];"
                 : "=r"(r[0]), "=r"(r[1]), "=r"(r[2]), "=r"(r[3]) : "r"(addr));
}
__device__ __forceinline__ void mma_bf16(float* c, const uint32_t* a, const uint32_t* b) {
    asm volatile("mma.sync.aligned.m16n8k16.row.col.f32.bf16.bf16.f32 "
                 "{%0,%1,%2,%3}, {%4,%5,%6,%7}, {%8,%9}, {%0,%1,%2,%3};"
                 : "+f"(c[0]), "+f"(c[1]), "+f"(c[2]), "+f"(c[3])
                 : "r"(a[0]), "r"(a[1]), "r"(a[2]), "r"(a[3]), "r"(b[0]), "r"(b[1]));
}

// ---------------- scratch (device globals; no allocation allowed) ----------------
// NOTE: these must ONLY be referenced from device code. Passing them as kernel
// arguments from host code silently resolves to the host shadow symbol (and on
// GB300/ATS writes land in host memory without trapping) — that was the R6/R7 bug.
__device__ __align__(16) float g_qkv[(size_t)B_ * S_ * TD];
__device__ __align__(16) float g_ao [(size_t)B_ * S_ * D_];
__device__ __align__(16) float g_qw [(size_t)B_ * H_ * S_ * KS];
__device__ __align__(16) float g_kw [(size_t)B_ * H_ * S_ * KS];
__device__ float g_mw [B_ * (S_-1)];
__device__ float g_im [B_ * (S_-1)];
// split-bf16 operands
__device__ __align__(16) __nv_bfloat16 g_xh [(size_t)B_ * S_ * D_];
__device__ __align__(16) __nv_bfloat16 g_xl [(size_t)B_ * S_ * D_];
__device__ __align__(16) __nv_bfloat16 g_wh [(size_t)TD * D_];
__device__ __align__(16) __nv_bfloat16 g_wl [(size_t)TD * D_];
__device__ __align__(16) __nv_bfloat16 g_aoh[(size_t)B_ * S_ * D_];
__device__ __align__(16) __nv_bfloat16 g_aol[(size_t)B_ * S_ * D_];
__device__ __align__(16) __nv_bfloat16 g_owh[(size_t)D_ * D_];
__device__ __align__(16) __nv_bfloat16 g_owl[(size_t)D_ * D_];

// ======================================================================
// fp32 -> (hi, lo) bf16 split. Device-resolved destinations.
// ======================================================================
__device__ __forceinline__ void split_body(const float* __restrict__ in,
                                           __nv_bfloat16* __restrict__ hi,
                                           __nv_bfloat16* __restrict__ lo, int n4)
{
    int i = blockIdx.x * blockDim.x + threadIdx.x;
    if (i >= n4) return;
    float4 v = ((const float4*)in)[i];
    float f[4] = {v.x, v.y, v.z, v.w};
    unsigned short hb[4], lb[4];
    #pragma unroll
    for (int j = 0; j < 4; ++j) {
        __nv_bfloat16 h = __float2bfloat16(f[j]);
        float hf = __bfloat162float(h);
        __nv_bfloat16 l = __float2bfloat16(f[j] - hf);
        hb[j] = __bfloat16_as_ushort(h);
        lb[j] = __bfloat16_as_ushort(l);
    }
    ((ushort4*)hi)[i] = make_ushort4(hb[0], hb[1], hb[2], hb[3]);
    ((ushort4*)lo)[i] = make_ushort4(lb[0], lb[1], lb[2], lb[3]);
}

__global__ __launch_bounds__(256)
void split_x_kernel(const float* __restrict__ in)
{ split_body(in, g_xh, g_xl, (B_ * S_ * D_) / 4); }

__global__ __launch_bounds__(256)
void split_w_kernel(const float* __restrict__ in)
{ split_body(in, g_wh, g_wl, (TD * D_) / 4); }

__global__ __launch_bounds__(256)
void split_ow_kernel(const float* __restrict__ in)
{ split_body(in, g_owh, g_owl, (D_ * D_) / 4); }

__global__ __launch_bounds__(256)
void split_ao_kernel()
{ split_body(g_ao, g_aoh, g_aol, (B_ * S_ * D_) / 4); }

// ======================================================================
// HMMA split-bf16 GEMM: C[M,N] = A[M,K]*B[N,K]^T, fp32 out
// 128x128 CTA tile, 8 warps (64x32 each), K-chunk 32, single-stage SMEM
// (40960 B < 48KB default). Rows padded to 80 B for conflict-free ldmatrix.
// ======================================================================
#define RSB   80                    // row stride bytes in smem
#define ARR_B (128 * RSB)           // 10240 B per operand array
#define TC_SMEM_BYTES (4 * ARR_B)   // 40960 B single stage

__device__ __forceinline__ void hmma_gemm_body(
    const __nv_bfloat16* __restrict__ Ah, const __nv_bfloat16* __restrict__ Al,
    const __nv_bfloat16* __restrict__ Bh, const __nv_bfloat16* __restrict__ Bl,
    float* __restrict__ C, int N)
{
    extern __shared__ char smem_raw[];
    const uint32_t base = smem_u32(smem_raw);

    const int tid  = threadIdx.x;
    const int lane = tid & 31;
    const int warp = tid >> 5;
    const int wm = warp >> 2;          // 0..1
    const int wn = warp & 3;           // 0..3
    const int m0 = blockIdx.y * 128;
    const int n0 = blockIdx.x * 128;

    // ldmatrix per-lane address pieces
    const int j   = lane >> 3;         // matrix index 0..3
    const int rin = lane & 7;
    const uint32_t a_row = wm * 64 + ((j & 1) << 3) + rin;
    const uint32_t a_kb  = (j >> 1) << 4;
    const uint32_t b_row = wn * 32 + ((j >> 1) << 3) + rin;
    const uint32_t b_kb  = (j & 1) << 4;

    const int g_row0 = tid >> 2;        // rows 0..63
    const int g_cg   = tid & 3;         // 16B group 0..3

    float acc[4][4][4];
    #pragma unroll
    for (int mi = 0; mi < 4; ++mi)
        #pragma unroll
        for (int ni = 0; ni < 4; ++ni)
            #pragma unroll
            for (int q = 0; q < 4; ++q) acc[mi][ni][q] = 0.f;

    const __nv_bfloat16* srcs[4] = { Ah, Al, Bh, Bl };

    // ---- preload chunk 0 ----
    #pragma unroll
    for (int arr = 0; arr < 4; ++arr) {
        const __nv_bfloat16* src = srcs[arr];
        const int rbase = (arr < 2) ? m0 : n0;
        #pragma unroll
        for (int i = 0; i < 2; ++i) {
            int row = g_row0 + i * 64;
            size_t go = (size_t)(rbase + row) * KDIM + g_cg * 8;
            uint4 v = *(const uint4*)(src + go);
            uint32_t sa = base + arr * ARR_B + row * RSB + g_cg * 16;
            asm volatile("st.shared.v4.b32 [%0], {%1,%2,%3,%4};"
                         :: "r"(sa), "r"(v.x), "r"(v.y), "r"(v.z), "r"(v.w) : "memory");
        }
    }
    __syncthreads();

    const int CH = KDIM / 32;   // 32 chunks
    for (int c = 0; c < CH; ++c) {
        // prefetch next chunk into regs
        uint4 pre[4][2];
        const bool more = (c + 1 < CH);
        if (more) {
            #pragma unroll
            for (int arr = 0; arr < 4; ++arr) {
                const __nv_bfloat16* src = srcs[arr];
                const int rbase = (arr < 2) ? m0 : n0;
                #pragma unroll
                for (int i = 0; i < 2; ++i) {
                    int row = g_row0 + i * 64;
                    size_t go = (size_t)(rbase + row) * KDIM + (c + 1) * 32 + g_cg * 8;
                    pre[arr][i] = *(const uint4*)(src + go);
                }
            }
        }

        // compute: 2 k16 steps from the single stage
        #pragma unroll
        for (int ks = 0; ks < 2; ++ks) {
            const uint32_t kbo = ks * 32;
            uint32_t ah[4][4], al[4][4], bh[4][2], bl[4][2];
            #pragma unroll
            for (int mi = 0; mi < 4; ++mi) {
                uint32_t addr = base + (a_row + mi * 16) * RSB + kbo + a_kb;
                ldsm4(addr, ah[mi]);
                ldsm4(addr + ARR_B, al[mi]);
            }
            #pragma unroll
            for (int p = 0; p < 2; ++p) {
                uint32_t addr = base + 2 * ARR_B + (b_row + p * 16) * RSB + kbo + b_kb;
                uint32_t rh[4], rl[4];
                ldsm4(addr, rh);
                ldsm4(addr + ARR_B, rl);
                bh[p*2+0][0] = rh[0]; bh[p*2+0][1] = rh[1];
                bh[p*2+1][0] = rh[2]; bh[p*2+1][1] = rh[3];
                bl[p*2+0][0] = rl[0]; bl[p*2+0][1] = rl[1];
                bl[p*2+1][0] = rl[2]; bl[p*2+1][1] = rl[3];
            }
            #pragma unroll
            for (int mi = 0; mi < 4; ++mi)
                #pragma unroll
                for (int ni = 0; ni < 4; ++ni) {
                    mma_bf16(acc[mi][ni], ah[mi], bh[ni]);
                    mma_bf16(acc[mi][ni], al[mi], bh[ni]);
                    mma_bf16(acc[mi][ni], ah[mi], bl[ni]);
                }
        }
        __syncthreads();            // all reads of this chunk done

        if (more) {
            #pragma unroll
            for (int arr = 0; arr < 4; ++arr)
                #pragma unroll
                for (int i = 0; i < 2; ++i) {
                    int row = g_row0 + i * 64;
                    uint32_t sa = base + arr * ARR_B + row * RSB + g_cg * 16;
                    uint4 v = pre[arr][i];
                    asm volatile("st.shared.v4.b32 [%0], {%1,%2,%3,%4};"
                                 :: "r"(sa), "r"(v.x), "r"(v.y), "r"(v.z), "r"(v.w) : "memory");
                }
            __syncthreads();        // stores visible before next compute
        }
    }

    // epilogue
    const int qr = lane >> 2;
    const int qc = (lane & 3) * 2;
    #pragma unroll
    for (int mi = 0; mi < 4; ++mi) {
        #pragma unroll
        for (int ni = 0; ni < 4; ++ni) {
            int r  = m0 + wm * 64 + mi * 16 + qr;
            int cc = n0 + wn * 32 + ni * 8 + qc;
            *(float2*)(C + (size_t)r * N + cc)       = make_float2(acc[mi][ni][0], acc[mi][ni][1]);
            *(float2*)(C + (size_t)(r + 8) * N + cc) = make_float2(acc[mi][ni][2], acc[mi][ni][3]);
        }
    }
}

__global__ __launch_bounds__(256, 1)
void hmma_gemm_qkv_kernel()
{
    hmma_gemm_body(g_xh, g_xl, g_wh, g_wl, g_qkv, TD);
}

__global__ __launch_bounds__(256, 1)
void hmma_gemm_out_kernel(float* __restrict__ out)
{
    hmma_gemm_body(g_aoh, g_aol, g_owh, g_owl, out, D_);
}

// ======================================================================
// Trajectory kernels
// ======================================================================
__global__ void traj_mag_kernel(const float* __restrict__ x)
{
    int gw   = (blockIdx.x * blockDim.x + threadIdx.x) >> 5;
    int lane = threadIdx.x & 31;
    if (gw >= B_ * (S_ - 1)) return;
    int b = gw / (S_ - 1);
    int j = gw % (S_ - 1);
    const float* r0 = x + ((size_t)b * S_ + j) * D_;
    const float* r1 = r0 + D_;
    float ss = 0.f;
    #pragma unroll
    for (int it = 0; it < D_ / (32 * 4); ++it) {
        int d = lane * 4 + it * 128;
        float4 a = *(const float4*)(r0 + d);
        float4 c = *(const float4*)(r1 + d);
        float dx = c.x - a.x, dy = c.y - a.y, dz = c.z - a.z, dw = c.w - a.w;
        ss += dx*dx + dy*dy + dz*dz + dw*dw;
    }
    #pragma unroll
    for (int o = 16; o; o >>= 1) ss += __shfl_xor_sync(0xffffffffu, ss, o);
    if (lane == 0) {
        float mag = sqrtf(ss);
        g_im[b * (S_-1) + j] = 1.0f / fmaxf(mag, 1e-8f);
        g_mw[b * (S_-1) + j] = tanhf(mag);
    }
}

__global__ void traj_out_kernel(const float* __restrict__ x, float* __restrict__ traj)
{
    int p = blockIdx.x;
    int b = blockIdx.y;
    __shared__ float coef[IR];
    __shared__ int   sh_ws, sh_cnt;
    if (threadIdx.x == 0) {
        int ws  = p - IR; if (ws < 0) ws = 0;
        int cnt = p - ws;
        float wsz = (float)(cnt > 0 ? cnt : 1);
        float w[IR]; float sum = 0.f;
        for (int t = 0; t < cnt; ++t) {
            float wv = g_mw[b * (S_-1) + ws + t] * (float)(t + 1) / wsz;
            w[t] = wv; sum += wv;
        }
        float inv = 1.0f / fmaxf(sum, 1e-8f);
        for (int t = 0; t < cnt; ++t)
            coef[t] = w[t] * inv * g_im[b * (S_-1) + ws + t];
        sh_ws = ws; sh_cnt = cnt;
    }
    __syncthreads();
    int ws = sh_ws, cnt = sh_cnt;
    const float* xb = x + (size_t)b * S_ * D_;
    for (int d = threadIdx.x * 4; d < D_; d += blockDim.x * 4) {
        float4 a = make_float4(0.f, 0.f, 0.f, 0.f);
        for (int t = 0; t < cnt; ++t) {
            float c = coef[t];
            const float* r0 = xb + (size_t)(ws + t) * D_ + d;
            float4 u = *(const float4*)(r0);
            float4 v = *(const float4*)(r0 + D_);
            a.x += c * (v.x - u.x); a.y += c * (v.y - u.y);
            a.z += c * (v.z - u.z); a.w += c * (v.w - u.w);
        }
        *(float4*)(traj + ((size_t)b * S_ + p) * D_ + d) = a;
    }
}

// ======================================================================
// Splat weights (packed f32x2, fused q+k via blockIdx.z)
// ======================================================================
__global__ __launch_bounds__(256)
void splat_weights_kernel(const float* __restrict__ centers,
                          const float* __restrict__ lsc,
                          const float* __restrict__ amp)
{
    int z = blockIdx.z;
    int which = z & 1;
    int b = z >> 1;
    int h = blockIdx.y;
    int s0 = blockIdx.x * 128;
    int tid = threadIdx.x;
    int off = which ? D_ : 0;
    float* outp = which ? g_kw : g_qw;

    __shared__ __align__(16) float cs[KS][HD];
    __shared__ float cn[KS], fac[KS], am[KS];
    __shared__ __align__(16) float ts[128][HD];
    __shared__ float tn[128];

    #pragma unroll
    for (int it = 0; it < 4; ++it) {
        int idx = tid + it * 256;
        int kk = idx >> 6, d = idx & 63;
        cs[kk][d] = centers[((size_t)h * KS + kk) * HD + d];
    }
    if (tid < KS) {
        float ls = lsc[h * KS + tid];
        fac[tid] = -0.5f * __expf(-2.0f * ls);
        float a  = amp[h * KS + tid];
        am[tid]  = 1.0f / (1.0f + __expf(-a));
    }
    const float* bse = g_qkv + ((size_t)b * S_ + s0) * TD + off + h * HD;
    #pragma unroll
    for (int it = 0; it < 8; ++it) {
        int idx = tid + it * 256;
        int s = idx >> 4, c4 = (idx & 15) * 4;
        *(float4*)&ts[s][c4] = *(const float4*)(bse + (size_t)s * TD + c4);
    }
    __syncthreads();
    if (tid < KS) {
        float s = 0.f;
        #pragma unroll
        for (int d = 0; d < HD; ++d) { float c = cs[tid][d]; s += c * c; }
        cn[tid] = s;
    }
    if (tid < 128) {
        const u64* tp = (const u64*)&ts[tid][0];
        u64 acc = 0ull;
        #pragma unroll
        for (int d = 0; d < 32; ++d) acc = ffma2(tp[d], tp[d], acc);
        float2 u = up2(acc);
        tn[tid] = u.x + u.y;
    }
    __syncthreads();

    #pragma unroll
    for (int it = 0; it < 8; ++it) {
        int idx = tid + it * 256;
        int s = idx >> 4, kk = idx & 15;
        const u64* tp = (const u64*)&ts[s][0];
        const u64* cp = (const u64*)&cs[kk][0];
        u64 acc = 0ull;
        #pragma unroll
        for (int d = 0; d < 32; ++d) acc = ffma2(tp[d], cp[d], acc);
        float2 u = up2(acc);
        float cross = u.x + u.y;
        float dist = tn[s] - 2.0f * cross + cn[kk];
        outp[(((size_t)b * H_ + h) * S_ + s0 + s) * KS + kk] =
            __expf(fac[kk] * dist) * am[kk];
    }
}

// ======================================================================
// Fused attention (packed f32x2), 1 thread = 1 query row
// ======================================================================
__global__ __launch_bounds__(128)
void attn_kernel()
{
    int b  = blockIdx.z, h = blockIdx.y;
    int i0 = blockIdx.x * 128;
    int tid = threadIdx.x;

    __shared__ __align__(16) float kws[64][KS];
    __shared__ __align__(16) float vs[64][HD];

    const float* qwf = g_qw + (((size_t)b * H_ + h) * S_ + i0 + tid) * KS;
    u64 qwp[8];
    {
        const ulonglong2* qp = (const ulonglong2*)qwf;
        #pragma unroll
        for (int t = 0; t < 4; ++t) {
            ulonglong2 v = qp[t];
            qwp[2*t]   = v.x;
            qwp[2*t+1] = v.y;
        }
    }

    u64 accp[32];
    #pragma unroll
    for (int d = 0; d < 32; ++d) accp[d] = 0ull;
    float den = 0.f;

    const float* kwb = g_kw + ((size_t)b * H_ + h) * S_ * KS;
    const float* vb  = g_qkv + (size_t)b * S_ * TD + 2 * D_ + h * HD;

    for (int j0 = 0; j0 < S_; j0 += 64) {
        #pragma unroll
        for (int it = 0; it < 2; ++it) {
            int idx = tid + it * 128;
            int j = idx >> 2, c4 = (idx & 3) * 4;
            *(float4*)&kws[j][c4] = *(const float4*)(kwb + (size_t)(j0 + j) * KS + c4);
        }
        #pragma unroll
        for (int it = 0; it < 8; ++it) {
            int idx = tid + it * 128;
            int j = idx >> 4, c4 = (idx & 15) * 4;
            *(float4*)&vs[j][c4] = *(const float4*)(vb + (size_t)(j0 + j) * TD + c4);
        }
        __syncthreads();

        #pragma unroll 2
        for (int jj = 0; jj < 64; ++jj) {
            const u64* kp = (const u64*)&kws[jj][0];
            u64 zp = 0ull;
            #pragma unroll
            for (int t = 0; t < 8; ++t) zp = ffma2(qwp[t], kp[t], zp);
            float2 zu = up2(zp);
            float e = __expf(zu.x + zu.y);
            den += e;
            u64 ep = pk1(e);
            const u64* vp = (const u64*)&vs[jj][0];
            #pragma unroll
            for (int d = 0; d < 32; ++d)
                accp[d] = ffma2(ep, vp[d], accp[d]);
        }
        __syncthreads();
    }

    float inv = 1.0f / den;
    float* op = g_ao + ((size_t)b * S_ + i0 + tid) * D_ + h * HD;
    #pragma unroll
    for (int d2 = 0; d2 < 16; ++d2) {
        float2 a0 = up2(accp[2*d2]);
        float2 a1 = up2(accp[2*d2+1]);
        float4 o = make_float4(a0.x * inv, a0.y * inv, a1.x * inv, a1.y * inv);
        *(float4*)(op + 4*d2) = o;
    }
}

// ======================================================================
// launch
// ======================================================================
extern "C" void kernel_launch(void* const* d_in, const int* in_sizes, int n_in,
                              void* d_out, int out_size)
{
    const float* x       = (const float*)d_in[0];
    const float* qkv_w   = (const float*)d_in[1];
    const float* out_w   = (const float*)d_in[2];
    const float* centers = (const float*)d_in[3];
    const float* lsc     = (const float*)d_in[4];
    const float* amps    = (const float*)d_in[5];
    float* out = (float*)d_out;

    const int BSD = B_ * S_ * D_;

    // ---- split conversions (harness pointers in; device globals resolved
    //      inside device code — never pass __device__ symbols from host!) ----
    split_x_kernel <<<(BSD / 4 + 255) / 256, 256>>>(x);
    split_w_kernel <<<((TD * D_) / 4 + 255) / 256, 256>>>(qkv_w);
    split_ow_kernel<<<((D_ * D_) / 4 + 255) / 256, 256>>>(out_w);

    // ---- trajectories -> second half of d_out ----
    {
        int warps = B_ * (S_ - 1);
        int blocks = (warps * 32 + 127) / 128;
        traj_mag_kernel<<<blocks, 128>>>(x);
        if (out_size >= 2 * BSD) {
            traj_out_kernel<<<dim3(S_, B_), 256>>>(x, out + BSD);
        }
    }

    // ---- qkv projection (HMMA split-bf16) ----
    hmma_gemm_qkv_kernel<<<dim3(TD / 128, (B_ * S_) / 128), 256, TC_SMEM_BYTES>>>();

    // ---- splat weights ----
    splat_weights_kernel<<<dim3(S_ / 128, H_, 2 * B_), 256>>>(centers, lsc, amps);

    // ---- fused attention ----
    attn_kernel<<<dim3(S_ / 128, H_, B_), 128>>>();

    // ---- split attention output, then output projection ----
    split_ao_kernel<<<(BSD / 4 + 255) / 256, 256>>>();
    hmma_gemm_out_kernel<<<dim3(D_ / 128, (B_ * S_) / 128), 256, TC_SMEM_BYTES>>>(out);
}

// round 10
// speedup vs baseline: 4.7453x; 1.8627x over previous
#include <cuda_runtime.h>
#include <cuda_bf16.h>
#include <math.h>
#include <stdint.h>

// ---------------- problem constants (fixed shapes) ----------------
#define B_  2
#define S_  2048
#define D_  1024
#define H_  16
#define KS  16      // splats per head
#define HD  64      // head dim
#define TD  (3*D_)  // qkv row width = 3072
#define IR  8       // influence radius
#define KDIM 1024   // GEMM K for both projections

typedef unsigned long long u64;

// ---------------- packed f32x2 helpers ----------------
__device__ __forceinline__ u64 pk2(float lo, float hi) {
    u64 r; asm("mov.b64 %0, {%1, %2};" : "=l"(r) : "f"(lo), "f"(hi)); return r;
}
__device__ __forceinline__ float2 up2(u64 v) {
    float2 r; asm("mov.b64 {%0, %1}, %2;" : "=f"(r.x), "=f"(r.y) : "l"(v)); return r;
}
__device__ __forceinline__ u64 ffma2(u64 a, u64 b, u64 c) {
    u64 d; asm("fma.rn.f32x2 %0, %1, %2, %3;" : "=l"(d) : "l"(a), "l"(b), "l"(c));
    return d;
}

// ---------------- warp MMA helpers (sm_80 baseline PTX; runs on sm_103) ----
__device__ __forceinline__ uint32_t smem_u32(const void* p) {
    uint32_t a;
    asm("{ .reg .u64 t; cvta.to.shared.u64 t, %1; cvt.u32.u64 %0, t; }" : "=r"(a) : "l"(p));
    return a;
}
__device__ __forceinline__ void ldsm4(uint32_t addr, uint32_t* r) {
    asm volatile("ldmatrix.sync.aligned.m8n8.x4.shared.b16 {%0,%1,%2,%3}, [%4];"
                 : "=r"(r[0]), "=r"(r[1]), "=r"(r[2]), "=r"(r[3]) : "r"(addr));
}
__device__ __forceinline__ void ldsm4t(uint32_t addr, uint32_t* r) {
    asm volatile("ldmatrix.sync.aligned.m8n8.x4.trans.shared.b16 {%0,%1,%2,%3}, [%4];"
                 : "=r"(r[0]), "=r"(r[1]), "=r"(r[2]), "=r"(r[3]) : "r"(addr));
}
__device__ __forceinline__ void mma_bf16(float* c, const uint32_t* a, const uint32_t* b) {
    asm volatile("mma.sync.aligned.m16n8k16.row.col.f32.bf16.bf16.f32 "
                 "{%0,%1,%2,%3}, {%4,%5,%6,%7}, {%8,%9}, {%0,%1,%2,%3};"
                 : "+f"(c[0]), "+f"(c[1]), "+f"(c[2]), "+f"(c[3])
                 : "r"(a[0]), "r"(a[1]), "r"(a[2]), "r"(a[3]), "r"(b[0]), "r"(b[1]));
}
// pack two fp32 into bf16x2: low half = lo, high half = hi
__device__ __forceinline__ uint32_t cvt2bf(float lo, float hi) {
    uint32_t r; asm("cvt.rn.bf16x2.f32 %0, %1, %2;" : "=r"(r) : "f"(hi), "f"(lo)); return r;
}
__device__ __forceinline__ float bflo(uint32_t p) { return __uint_as_float(p << 16); }
__device__ __forceinline__ float bfhi(uint32_t p) { return __uint_as_float(p & 0xffff0000u); }

// ---------------- scratch (device globals; no allocation allowed) ----------------
// NOTE: reference these ONLY from device code (host-shadow pitfall, R6/R7).
__device__ __align__(16) float g_qkv[(size_t)B_ * S_ * TD];
__device__ float g_mw [B_ * (S_-1)];
__device__ float g_im [B_ * (S_-1)];
// split-bf16 operands
__device__ __align__(16) __nv_bfloat16 g_xh [(size_t)B_ * S_ * D_];
__device__ __align__(16) __nv_bfloat16 g_xl [(size_t)B_ * S_ * D_];
__device__ __align__(16) __nv_bfloat16 g_wh [(size_t)TD * D_];
__device__ __align__(16) __nv_bfloat16 g_wl [(size_t)TD * D_];
__device__ __align__(16) __nv_bfloat16 g_aoh[(size_t)B_ * S_ * D_];
__device__ __align__(16) __nv_bfloat16 g_aol[(size_t)B_ * S_ * D_];
__device__ __align__(16) __nv_bfloat16 g_owh[(size_t)D_ * D_];
__device__ __align__(16) __nv_bfloat16 g_owl[(size_t)D_ * D_];
// attention operands (bf16 hi/lo)
__device__ __align__(16) __nv_bfloat16 g_qwh[(size_t)B_ * H_ * S_ * KS];
__device__ __align__(16) __nv_bfloat16 g_qwl[(size_t)B_ * H_ * S_ * KS];
__device__ __align__(16) __nv_bfloat16 g_kwh[(size_t)B_ * H_ * S_ * KS];
__device__ __align__(16) __nv_bfloat16 g_kwl[(size_t)B_ * H_ * S_ * KS];
__device__ __align__(16) __nv_bfloat16 g_vh [(size_t)B_ * S_ * D_];
__device__ __align__(16) __nv_bfloat16 g_vl [(size_t)B_ * S_ * D_];

// ======================================================================
// fp32 -> (hi, lo) bf16 split
// ======================================================================
__device__ __forceinline__ void split_body(const float* __restrict__ in,
                                           __nv_bfloat16* __restrict__ hi,
                                           __nv_bfloat16* __restrict__ lo, int n4)
{
    int i = blockIdx.x * blockDim.x + threadIdx.x;
    if (i >= n4) return;
    float4 v = ((const float4*)in)[i];
    float f[4] = {v.x, v.y, v.z, v.w};
    unsigned short hb[4], lb[4];
    #pragma unroll
    for (int j = 0; j < 4; ++j) {
        __nv_bfloat16 h = __float2bfloat16(f[j]);
        float hf = __bfloat162float(h);
        __nv_bfloat16 l = __float2bfloat16(f[j] - hf);
        hb[j] = __bfloat16_as_ushort(h);
        lb[j] = __bfloat16_as_ushort(l);
    }
    ((ushort4*)hi)[i] = make_ushort4(hb[0], hb[1], hb[2], hb[3]);
    ((ushort4*)lo)[i] = make_ushort4(lb[0], lb[1], lb[2], lb[3]);
}

__global__ __launch_bounds__(256)
void split_x_kernel(const float* __restrict__ in)
{ split_body(in, g_xh, g_xl, (B_ * S_ * D_) / 4); }

__global__ __launch_bounds__(256)
void split_w_kernel(const float* __restrict__ in)
{ split_body(in, g_wh, g_wl, (TD * D_) / 4); }

__global__ __launch_bounds__(256)
void split_ow_kernel(const float* __restrict__ in)
{ split_body(in, g_owh, g_owl, (D_ * D_) / 4); }

// split the V section of g_qkv (strided rows) into g_vh/g_vl [B*S, D]
__global__ __launch_bounds__(256)
void split_v_kernel()
{
    const int n4 = (B_ * S_ * D_) / 4;
    int i = blockIdx.x * blockDim.x + threadIdx.x;
    if (i >= n4) return;
    int row = i >> 8;              // D_/4 = 256 quads per row
    int c4  = (i & 255) * 4;
    float4 v = *(const float4*)(g_qkv + (size_t)row * TD + 2 * D_ + c4);
    float f[4] = {v.x, v.y, v.z, v.w};
    unsigned short hb[4], lb[4];
    #pragma unroll
    for (int j = 0; j < 4; ++j) {
        __nv_bfloat16 h = __float2bfloat16(f[j]);
        float hf = __bfloat162float(h);
        __nv_bfloat16 l = __float2bfloat16(f[j] - hf);
        hb[j] = __bfloat16_as_ushort(h);
        lb[j] = __bfloat16_as_ushort(l);
    }
    *(ushort4*)(g_vh + (size_t)row * D_ + c4) = make_ushort4(hb[0], hb[1], hb[2], hb[3]);
    *(ushort4*)(g_vl + (size_t)row * D_ + c4) = make_ushort4(lb[0], lb[1], lb[2], lb[3]);
}

// ======================================================================
// HMMA split-bf16 GEMM: C[M,N] = A[M,K]*B[N,K]^T, fp32 out (R8, passing)
// ======================================================================
#define RSB   80
#define ARR_B (128 * RSB)
#define TC_SMEM_BYTES (4 * ARR_B)   // 40960 B

__device__ __forceinline__ void hmma_gemm_body(
    const __nv_bfloat16* __restrict__ Ah, const __nv_bfloat16* __restrict__ Al,
    const __nv_bfloat16* __restrict__ Bh, const __nv_bfloat16* __restrict__ Bl,
    float* __restrict__ C, int N)
{
    extern __shared__ char smem_raw[];
    const uint32_t base = smem_u32(smem_raw);

    const int tid  = threadIdx.x;
    const int lane = tid & 31;
    const int warp = tid >> 5;
    const int wm = warp >> 2;
    const int wn = warp & 3;
    const int m0 = blockIdx.y * 128;
    const int n0 = blockIdx.x * 128;

    const int j   = lane >> 3;
    const int rin = lane & 7;
    const uint32_t a_row = wm * 64 + ((j & 1) << 3) + rin;
    const uint32_t a_kb  = (j >> 1) << 4;
    const uint32_t b_row = wn * 32 + ((j >> 1) << 3) + rin;
    const uint32_t b_kb  = (j & 1) << 4;

    const int g_row0 = tid >> 2;
    const int g_cg   = tid & 3;

    float acc[4][4][4];
    #pragma unroll
    for (int mi = 0; mi < 4; ++mi)
        #pragma unroll
        for (int ni = 0; ni < 4; ++ni)
            #pragma unroll
            for (int q = 0; q < 4; ++q) acc[mi][ni][q] = 0.f;

    const __nv_bfloat16* srcs[4] = { Ah, Al, Bh, Bl };

    #pragma unroll
    for (int arr = 0; arr < 4; ++arr) {
        const __nv_bfloat16* src = srcs[arr];
        const int rbase = (arr < 2) ? m0 : n0;
        #pragma unroll
        for (int i = 0; i < 2; ++i) {
            int row = g_row0 + i * 64;
            size_t go = (size_t)(rbase + row) * KDIM + g_cg * 8;
            uint4 v = *(const uint4*)(src + go);
            uint32_t sa = base + arr * ARR_B + row * RSB + g_cg * 16;
            asm volatile("st.shared.v4.b32 [%0], {%1,%2,%3,%4};"
                         :: "r"(sa), "r"(v.x), "r"(v.y), "r"(v.z), "r"(v.w) : "memory");
        }
    }
    __syncthreads();

    const int CH = KDIM / 32;
    for (int c = 0; c < CH; ++c) {
        uint4 pre[4][2];
        const bool more = (c + 1 < CH);
        if (more) {
            #pragma unroll
            for (int arr = 0; arr < 4; ++arr) {
                const __nv_bfloat16* src = srcs[arr];
                const int rbase = (arr < 2) ? m0 : n0;
                #pragma unroll
                for (int i = 0; i < 2; ++i) {
                    int row = g_row0 + i * 64;
                    size_t go = (size_t)(rbase + row) * KDIM + (c + 1) * 32 + g_cg * 8;
                    pre[arr][i] = *(const uint4*)(src + go);
                }
            }
        }

        #pragma unroll
        for (int ks = 0; ks < 2; ++ks) {
            const uint32_t kbo = ks * 32;
            uint32_t ah[4][4], al[4][4], bh[4][2], bl[4][2];
            #pragma unroll
            for (int mi = 0; mi < 4; ++mi) {
                uint32_t addr = base + (a_row + mi * 16) * RSB + kbo + a_kb;
                ldsm4(addr, ah[mi]);
                ldsm4(addr + ARR_B, al[mi]);
            }
            #pragma unroll
            for (int p = 0; p < 2; ++p) {
                uint32_t addr = base + 2 * ARR_B + (b_row + p * 16) * RSB + kbo + b_kb;
                uint32_t rh[4], rl[4];
                ldsm4(addr, rh);
                ldsm4(addr + ARR_B, rl);
                bh[p*2+0][0] = rh[0]; bh[p*2+0][1] = rh[1];
                bh[p*2+1][0] = rh[2]; bh[p*2+1][1] = rh[3];
                bl[p*2+0][0] = rl[0]; bl[p*2+0][1] = rl[1];
                bl[p*2+1][0] = rl[2]; bl[p*2+1][1] = rl[3];
            }
            #pragma unroll
            for (int mi = 0; mi < 4; ++mi)
                #pragma unroll
                for (int ni = 0; ni < 4; ++ni) {
                    mma_bf16(acc[mi][ni], ah[mi], bh[ni]);
                    mma_bf16(acc[mi][ni], al[mi], bh[ni]);
                    mma_bf16(acc[mi][ni], ah[mi], bl[ni]);
                }
        }
        __syncthreads();

        if (more) {
            #pragma unroll
            for (int arr = 0; arr < 4; ++arr)
                #pragma unroll
                for (int i = 0; i < 2; ++i) {
                    int row = g_row0 + i * 64;
                    uint32_t sa = base + arr * ARR_B + row * RSB + g_cg * 16;
                    uint4 v = pre[arr][i];
                    asm volatile("st.shared.v4.b32 [%0], {%1,%2,%3,%4};"
                                 :: "r"(sa), "r"(v.x), "r"(v.y), "r"(v.z), "r"(v.w) : "memory");
                }
            __syncthreads();
        }
    }

    const int qr = lane >> 2;
    const int qc = (lane & 3) * 2;
    #pragma unroll
    for (int mi = 0; mi < 4; ++mi) {
        #pragma unroll
        for (int ni = 0; ni < 4; ++ni) {
            int r  = m0 + wm * 64 + mi * 16 + qr;
            int cc = n0 + wn * 32 + ni * 8 + qc;
            *(float2*)(C + (size_t)r * N + cc)       = make_float2(acc[mi][ni][0], acc[mi][ni][1]);
            *(float2*)(C + (size_t)(r + 8) * N + cc) = make_float2(acc[mi][ni][2], acc[mi][ni][3]);
        }
    }
}

__global__ __launch_bounds__(256, 1)
void hmma_gemm_qkv_kernel()
{
    hmma_gemm_body(g_xh, g_xl, g_wh, g_wl, g_qkv, TD);
}

__global__ __launch_bounds__(256, 1)
void hmma_gemm_out_kernel(float* __restrict__ out)
{
    hmma_gemm_body(g_aoh, g_aol, g_owh, g_owl, out, D_);
}

// ======================================================================
// Trajectory kernels
// ======================================================================
__global__ void traj_mag_kernel(const float* __restrict__ x)
{
    int gw   = (blockIdx.x * blockDim.x + threadIdx.x) >> 5;
    int lane = threadIdx.x & 31;
    if (gw >= B_ * (S_ - 1)) return;
    int b = gw / (S_ - 1);
    int j = gw % (S_ - 1);
    const float* r0 = x + ((size_t)b * S_ + j) * D_;
    const float* r1 = r0 + D_;
    float ss = 0.f;
    #pragma unroll
    for (int it = 0; it < D_ / (32 * 4); ++it) {
        int d = lane * 4 + it * 128;
        float4 a = *(const float4*)(r0 + d);
        float4 c = *(const float4*)(r1 + d);
        float dx = c.x - a.x, dy = c.y - a.y, dz = c.z - a.z, dw = c.w - a.w;
        ss += dx*dx + dy*dy + dz*dz + dw*dw;
    }
    #pragma unroll
    for (int o = 16; o; o >>= 1) ss += __shfl_xor_sync(0xffffffffu, ss, o);
    if (lane == 0) {
        float mag = sqrtf(ss);
        g_im[b * (S_-1) + j] = 1.0f / fmaxf(mag, 1e-8f);
        g_mw[b * (S_-1) + j] = tanhf(mag);
    }
}

__global__ void traj_out_kernel(const float* __restrict__ x, float* __restrict__ traj)
{
    int p = blockIdx.x;
    int b = blockIdx.y;
    __shared__ float coef[IR];
    __shared__ int   sh_ws, sh_cnt;
    if (threadIdx.x == 0) {
        int ws  = p - IR; if (ws < 0) ws = 0;
        int cnt = p - ws;
        float wsz = (float)(cnt > 0 ? cnt : 1);
        float w[IR]; float sum = 0.f;
        for (int t = 0; t < cnt; ++t) {
            float wv = g_mw[b * (S_-1) + ws + t] * (float)(t + 1) / wsz;
            w[t] = wv; sum += wv;
        }
        float inv = 1.0f / fmaxf(sum, 1e-8f);
        for (int t = 0; t < cnt; ++t)
            coef[t] = w[t] * inv * g_im[b * (S_-1) + ws + t];
        sh_ws = ws; sh_cnt = cnt;
    }
    __syncthreads();
    int ws = sh_ws, cnt = sh_cnt;
    const float* xb = x + (size_t)b * S_ * D_;
    for (int d = threadIdx.x * 4; d < D_; d += blockDim.x * 4) {
        float4 a = make_float4(0.f, 0.f, 0.f, 0.f);
        for (int t = 0; t < cnt; ++t) {
            float c = coef[t];
            const float* r0 = xb + (size_t)(ws + t) * D_ + d;
            float4 u = *(const float4*)(r0);
            float4 v = *(const float4*)(r0 + D_);
            a.x += c * (v.x - u.x); a.y += c * (v.y - u.y);
            a.z += c * (v.z - u.z); a.w += c * (v.w - u.w);
        }
        *(float4*)(traj + ((size_t)b * S_ + p) * D_ + d) = a;
    }
}

// ======================================================================
// Splat weights -> bf16 hi/lo directly (packed f32x2 math, fused q+k)
// ======================================================================
__global__ __launch_bounds__(256)
void splat_weights_kernel(const float* __restrict__ centers,
                          const float* __restrict__ lsc,
                          const float* __restrict__ amp)
{
    int z = blockIdx.z;
    int which = z & 1;
    int b = z >> 1;
    int h = blockIdx.y;
    int s0 = blockIdx.x * 128;
    int tid = threadIdx.x;
    int off = which ? D_ : 0;

    __shared__ __align__(16) float cs[KS][HD];
    __shared__ float cn[KS], fac[KS], am[KS];
    __shared__ __align__(16) float ts[128][HD];
    __shared__ float tn[128];

    #pragma unroll
    for (int it = 0; it < 4; ++it) {
        int idx = tid + it * 256;
        int kk = idx >> 6, d = idx & 63;
        cs[kk][d] = centers[((size_t)h * KS + kk) * HD + d];
    }
    if (tid < KS) {
        float ls = lsc[h * KS + tid];
        fac[tid] = -0.5f * __expf(-2.0f * ls);
        float a  = amp[h * KS + tid];
        am[tid]  = 1.0f / (1.0f + __expf(-a));
    }
    const float* bse = g_qkv + ((size_t)b * S_ + s0) * TD + off + h * HD;
    #pragma unroll
    for (int it = 0; it < 8; ++it) {
        int idx = tid + it * 256;
        int s = idx >> 4, c4 = (idx & 15) * 4;
        *(float4*)&ts[s][c4] = *(const float4*)(bse + (size_t)s * TD + c4);
    }
    __syncthreads();
    if (tid < KS) {
        float s = 0.f;
        #pragma unroll
        for (int d = 0; d < HD; ++d) { float c = cs[tid][d]; s += c * c; }
        cn[tid] = s;
    }
    if (tid < 128) {
        const u64* tp = (const u64*)&ts[tid][0];
        u64 acc = 0ull;
        #pragma unroll
        for (int d = 0; d < 32; ++d) acc = ffma2(tp[d], tp[d], acc);
        float2 u = up2(acc);
        tn[tid] = u.x + u.y;
    }
    __syncthreads();

    #pragma unroll
    for (int it = 0; it < 8; ++it) {
        int idx = tid + it * 256;
        int s = idx >> 4, kk = idx & 15;
        const u64* tp = (const u64*)&ts[s][0];
        const u64* cp = (const u64*)&cs[kk][0];
        u64 acc = 0ull;
        #pragma unroll
        for (int d = 0; d < 32; ++d) acc = ffma2(tp[d], cp[d], acc);
        float2 u = up2(acc);
        float cross = u.x + u.y;
        float dist = tn[s] - 2.0f * cross + cn[kk];
        float w = __expf(fac[kk] * dist) * am[kk];
        __nv_bfloat16 hh = __float2bfloat16(w);
        float hf = __bfloat162float(hh);
        __nv_bfloat16 hl = __float2bfloat16(w - hf);
        size_t o = (((size_t)b * H_ + h) * S_ + s0 + s) * KS + kk;
        if (which) { g_kwh[o] = hh; g_kwl[o] = hl; }
        else       { g_qwh[o] = hh; g_qwl[o] = hl; }
    }
}

// ======================================================================
// HMMA flash attention. CTA = 64 queries of one (b,h); 4 warps x 16 q.
// QK: split-bf16 3-product m16n8k16; exp on fp32 C-frags (no max-sub
// needed: logits in [0,16]); P split hi/lo packed directly into A-frags;
// PV: 3-product with V hi/lo via ldsm.trans. Epilogue writes aoh/aol.
// ======================================================================
__global__ __launch_bounds__(128, 1)
void attn_mma_kernel()
{
    const int b = blockIdx.z, h = blockIdx.y;
    const int tid = threadIdx.x, lane = tid & 31, warp = tid >> 5;
    const int q0 = blockIdx.x * 64 + warp * 16;

    __shared__ __align__(16) __nv_bfloat16 skh[64][24];   // kw hi, 48B rows
    __shared__ __align__(16) __nv_bfloat16 skl[64][24];   // kw lo
    __shared__ __align__(16) __nv_bfloat16 svh[64][72];   // V hi, 144B rows
    __shared__ __align__(16) __nv_bfloat16 svl[64][72];   // V lo

    const int r4 = lane >> 2;
    const int c2 = (lane & 3) * 2;

    // persistent Q fragments (A-frag [16q x 16k])
    uint32_t qh[4], ql[4];
    {
        const __nv_bfloat16* qhb = g_qwh + (((size_t)b * H_ + h) * S_ + q0) * KS;
        const __nv_bfloat16* qlb = g_qwl + (((size_t)b * H_ + h) * S_ + q0) * KS;
        qh[0] = *(const uint32_t*)(qhb + (size_t)r4 * KS + c2);
        qh[1] = *(const uint32_t*)(qhb + (size_t)(r4 + 8) * KS + c2);
        qh[2] = *(const uint32_t*)(qhb + (size_t)r4 * KS + c2 + 8);
        qh[3] = *(const uint32_t*)(qhb + (size_t)(r4 + 8) * KS + c2 + 8);
        ql[0] = *(const uint32_t*)(qlb + (size_t)r4 * KS + c2);
        ql[1] = *(const uint32_t*)(qlb + (size_t)(r4 + 8) * KS + c2);
        ql[2] = *(const uint32_t*)(qlb + (size_t)r4 * KS + c2 + 8);
        ql[3] = *(const uint32_t*)(qlb + (size_t)(r4 + 8) * KS + c2 + 8);
    }

    float acc[8][4];
    #pragma unroll
    for (int i = 0; i < 8; ++i)
        #pragma unroll
        for (int q = 0; q < 4; ++q) acc[i][q] = 0.f;
    float den0 = 0.f, den1 = 0.f;

    // ldsm address pieces
    const int jj  = lane >> 3, rin = lane & 7;
    const int k_row = ((jj >> 1) << 3) + rin;       // row within 16-j tile
    const int k_col = (jj & 1) * 8;                 // element offset (16B)
    const int v_row = lane & 15;
    const int v_col = (lane >> 4) * 8;

    const size_t kw_base = (((size_t)b * H_ + h) * S_) * KS;
    const size_t v_base  = ((size_t)b * S_) * D_ + h * HD;

    for (int j0 = 0; j0 < S_; j0 += 64) {
        // ---- stage kw + V tiles ----
        {
            int row = tid >> 1, part = tid & 1;
            size_t gk = kw_base + (size_t)(j0 + row) * KS + part * 8;
            *(uint4*)&skh[row][part * 8] = *(const uint4*)(g_kwh + gk);
            *(uint4*)&skl[row][part * 8] = *(const uint4*)(g_kwl + gk);
        }
        #pragma unroll
        for (int i = 0; i < 4; ++i) {
            int idx = tid + i * 128;
            int row = idx >> 3, seg = idx & 7;
            size_t gv = v_base + (size_t)(j0 + row) * D_ + seg * 8;
            *(uint4*)&svh[row][seg * 8] = *(const uint4*)(g_vh + gv);
            *(uint4*)&svl[row][seg * 8] = *(const uint4*)(g_vl + gv);
        }
        __syncthreads();

        #pragma unroll
        for (int jt = 0; jt < 4; ++jt) {
            // kw B-frags (hi, lo)
            uint32_t kh[4], kl[4];
            ldsm4(smem_u32(&skh[jt * 16 + k_row][k_col]), kh);
            ldsm4(smem_u32(&skl[jt * 16 + k_row][k_col]), kl);

            float cz0[4] = {0.f, 0.f, 0.f, 0.f};
            float cz1[4] = {0.f, 0.f, 0.f, 0.f};
            mma_bf16(cz0, qh, kh);      // kh[0],kh[1] = n-tile j0-7
            mma_bf16(cz0, ql, kh);
            mma_bf16(cz0, qh, kl);
            mma_bf16(cz1, qh, kh + 2);  // kh[2],kh[3] = n-tile j8-15
            mma_bf16(cz1, ql, kh + 2);
            mma_bf16(cz1, qh, kl + 2);

            // exp (logits in [0,16], no max subtraction needed)
            float e00 = __expf(cz0[0]), e01 = __expf(cz0[1]);
            float e02 = __expf(cz0[2]), e03 = __expf(cz0[3]);
            float e10 = __expf(cz1[0]), e11 = __expf(cz1[1]);
            float e12 = __expf(cz1[2]), e13 = __expf(cz1[3]);
            den0 += e00 + e01 + e10 + e11;
            den1 += e02 + e03 + e12 + e13;

            // P A-frags: hi + residual lo
            uint32_t ph[4], pl[4];
            ph[0] = cvt2bf(e00, e01);
            ph[1] = cvt2bf(e02, e03);
            ph[2] = cvt2bf(e10, e11);
            ph[3] = cvt2bf(e12, e13);
            pl[0] = cvt2bf(e00 - bflo(ph[0]), e01 - bfhi(ph[0]));
            pl[1] = cvt2bf(e02 - bflo(ph[1]), e03 - bfhi(ph[1]));
            pl[2] = cvt2bf(e10 - bflo(ph[2]), e11 - bfhi(ph[2]));
            pl[3] = cvt2bf(e12 - bflo(ph[3]), e13 - bfhi(ph[3]));

            // PV: 4 ldsm.trans pairs cover d 0..63
            #pragma unroll
            for (int dp = 0; dp < 4; ++dp) {
                uint32_t vh[4], vl[4];
                ldsm4t(smem_u32(&svh[jt * 16 + v_row][dp * 16 + v_col]), vh);
                ldsm4t(smem_u32(&svl[jt * 16 + v_row][dp * 16 + v_col]), vl);
                mma_bf16(acc[dp * 2],     ph, vh);
                mma_bf16(acc[dp * 2],     pl, vh);
                mma_bf16(acc[dp * 2],     ph, vl);
                mma_bf16(acc[dp * 2 + 1], ph, vh + 2);
                mma_bf16(acc[dp * 2 + 1], pl, vh + 2);
                mma_bf16(acc[dp * 2 + 1], ph, vl + 2);
            }
        }
        __syncthreads();
    }

    // reduce denominators within quads (lanes sharing q-row)
    den0 += __shfl_xor_sync(0xffffffffu, den0, 1);
    den0 += __shfl_xor_sync(0xffffffffu, den0, 2);
    den1 += __shfl_xor_sync(0xffffffffu, den1, 1);
    den1 += __shfl_xor_sync(0xffffffffu, den1, 2);
    float inv0 = 1.0f / den0;
    float inv1 = 1.0f / den1;

    // epilogue: normalize + write bf16 hi/lo splits directly
    size_t row_a = ((size_t)b * S_ + q0 + r4) * D_ + h * HD;
    size_t row_b = ((size_t)b * S_ + q0 + r4 + 8) * D_ + h * HD;
    #pragma unroll
    for (int db = 0; db < 8; ++db) {
        int dc = db * 8 + c2;
        float o0 = acc[db][0] * inv0, o1 = acc[db][1] * inv0;
        float o2 = acc[db][2] * inv1, o3 = acc[db][3] * inv1;
        uint32_t h01 = cvt2bf(o0, o1), h23 = cvt2bf(o2, o3);
        uint32_t l01 = cvt2bf(o0 - bflo(h01), o1 - bfhi(h01));
        uint32_t l23 = cvt2bf(o2 - bflo(h23), o3 - bfhi(h23));
        *(uint32_t*)(g_aoh + row_a + dc) = h01;
        *(uint32_t*)(g_aoh + row_b + dc) = h23;
        *(uint32_t*)(g_aol + row_a + dc) = l01;
        *(uint32_t*)(g_aol + row_b + dc) = l23;
    }
}

// ======================================================================
// launch
// ======================================================================
extern "C" void kernel_launch(void* const* d_in, const int* in_sizes, int n_in,
                              void* d_out, int out_size)
{
    const float* x       = (const float*)d_in[0];
    const float* qkv_w   = (const float*)d_in[1];
    const float* out_w   = (const float*)d_in[2];
    const float* centers = (const float*)d_in[3];
    const float* lsc     = (const float*)d_in[4];
    const float* amps    = (const float*)d_in[5];
    float* out = (float*)d_out;

    const int BSD = B_ * S_ * D_;

    // ---- input splits ----
    split_x_kernel <<<(BSD / 4 + 255) / 256, 256>>>(x);
    split_w_kernel <<<((TD * D_) / 4 + 255) / 256, 256>>>(qkv_w);
    split_ow_kernel<<<((D_ * D_) / 4 + 255) / 256, 256>>>(out_w);

    // ---- trajectories -> second half of d_out ----
    {
        int warps = B_ * (S_ - 1);
        int blocks = (warps * 32 + 127) / 128;
        traj_mag_kernel<<<blocks, 128>>>(x);
        if (out_size >= 2 * BSD) {
            traj_out_kernel<<<dim3(S_, B_), 256>>>(x, out + BSD);
        }
    }

    // ---- qkv projection ----
    hmma_gemm_qkv_kernel<<<dim3(TD / 128, (B_ * S_) / 128), 256, TC_SMEM_BYTES>>>();

    // ---- splat weights (bf16 hi/lo) + V split ----
    splat_weights_kernel<<<dim3(S_ / 128, H_, 2 * B_), 256>>>(centers, lsc, amps);
    split_v_kernel<<<(BSD / 4 + 255) / 256, 256>>>();

    // ---- HMMA flash attention (writes aoh/aol) ----
    attn_mma_kernel<<<dim3(S_ / 64, H_, B_), 128>>>();

    // ---- output projection ----
    hmma_gemm_out_kernel<<<dim3(D_ / 128, (B_ * S_) / 128), 256, TC_SMEM_BYTES>>>(out);
}